// round 9
// baseline (speedup 1.0000x reference)
#include <cuda_runtime.h>
#include <cuda_bf16.h>
#include <cstdint>

// Inputs (metadata order):
//   d_in[0] weight : float32 [N_NODES * 128]
//   d_in[1] cj     : float32 [N_NODES]
//   d_in[2] ci     : float32 [N_NODES]
//   d_in[3] src    : int32   [N_EDGES]
//   d_in[4] dst    : int32   [N_EDGES]
// Output: float32 [N_NODES * 128]
//
// h[d] = ci[d] * sum_{e: dst_e = d} weight[src_e] * cj[src_e]
//
// 4-kernel pipeline, fully free of inter-block spin-waits:
//   k_hist    : int4 histogram of dst; stores each edge's rank (the
//               atomicAdd return) coalesced into g_rank
//   k_scan    : SINGLE-BLOCK exclusive scan (1024 threads, ~98 elems each);
//               no cross-block communication -> cannot deadlock under any
//               scheduling, graph-capture, or replay condition
//   k_scatter : pos = offsets[dst] + rank (plain loads, no atomics)
//   k_gather  : one warp per dst node; per-edge broadcast id/cj loads,
//               4-deep unrolled float4 gathers, register accumulate, 1 store

static constexpr int MAX_NODES = 100000;
static constexpr int MAX_EDGES = 1600000;
static constexpr int FEAT4     = 32;            // 128 floats = 32 float4

__device__ int g_counts[MAX_NODES];             // zero-init; re-zeroed by gather
__device__ int g_offsets[MAX_NODES];            // segment start
__device__ int g_cursor[MAX_NODES];             // segment end
__device__ int g_rank[MAX_EDGES];               // per-edge rank within its dst
__device__ int g_edge_src[MAX_EDGES];           // dst-sorted src ids

// ---------------- histogram with rank capture ----------------

__global__ void __launch_bounds__(256)
k_hist(const int4* __restrict__ dst4, int n_quads,
       const int* __restrict__ dst, int n_edges)
{
    int q = blockIdx.x * 256 + threadIdx.x;
    if (q < n_quads) {
        int4 d = __ldg(dst4 + q);
        int4 r;
        r.x = atomicAdd(&g_counts[d.x], 1);
        r.y = atomicAdd(&g_counts[d.y], 1);
        r.z = atomicAdd(&g_counts[d.z], 1);
        r.w = atomicAdd(&g_counts[d.w], 1);
        ((int4*)g_rank)[q] = r;                  // coalesced rank store
    }
    int t = n_quads * 4 + q;
    if (q < (n_edges - n_quads * 4))
        g_rank[t] = atomicAdd(&g_counts[dst[t]], 1);
}

// ---------------- single-block exclusive scan ----------------
// One block of 1024 threads. Thread t owns the contiguous chunk
// [t*C, min((t+1)*C, n)) with C = ceil(n/1024) (~98 for n=100000).
// Pass 1: per-thread chunk sum. Block scan of the 1024 sums (shfl + smem).
// Pass 2: per-thread running prefix writes offsets (start) / cursor (end).
// No inter-block communication of any kind.

__global__ void __launch_bounds__(1024)
k_scan(int n) {
    __shared__ int warp_sums[32];
    const int T = 1024;
    int tid  = threadIdx.x;
    int lane = tid & 31, wid = tid >> 5;

    int C  = (n + T - 1) / T;
    int lo = tid * C;
    int hi = lo + C; if (hi > n) hi = n;

    // pass 1: chunk sum
    int sum = 0;
    for (int i = lo; i < hi; i++) sum += g_counts[i];

    // block inclusive scan of per-thread sums
    int x = sum;
    #pragma unroll
    for (int o = 1; o < 32; o <<= 1) {
        int y = __shfl_up_sync(0xFFFFFFFFu, x, o);
        if (lane >= o) x += y;
    }
    if (lane == 31) warp_sums[wid] = x;
    __syncthreads();

    if (wid == 0) {
        int w = warp_sums[lane];
        #pragma unroll
        for (int o = 1; o < 32; o <<= 1) {
            int y = __shfl_up_sync(0xFFFFFFFFu, w, o);
            if (lane >= o) w += y;
        }
        warp_sums[lane] = w;                     // inclusive warp-total prefix
    }
    __syncthreads();

    int warp_off = (wid > 0) ? warp_sums[wid - 1] : 0;
    int run = warp_off + x - sum;                // exclusive prefix for this chunk

    // pass 2: write segment starts/ends
    for (int i = lo; i < hi; i++) {
        int v = g_counts[i];
        g_offsets[i] = run;
        g_cursor[i]  = run + v;
        run += v;
    }
}

// ---------------- scatter (atomic-free) ----------------

__global__ void __launch_bounds__(256)
k_scatter(const int4* __restrict__ src4,
          const int4* __restrict__ dst4, int n_quads,
          const int* __restrict__ src,
          const int* __restrict__ dst, int n_edges)
{
    int q = blockIdx.x * 256 + threadIdx.x;
    if (q < n_quads) {
        int4 s = __ldg(src4 + q);
        int4 d = __ldg(dst4 + q);
        int4 r = ((const int4*)g_rank)[q];
        g_edge_src[g_offsets[d.x] + r.x] = s.x;
        g_edge_src[g_offsets[d.y] + r.y] = s.y;
        g_edge_src[g_offsets[d.z] + r.z] = s.z;
        g_edge_src[g_offsets[d.w] + r.w] = s.w;
    }
    int t = n_quads * 4 + q;
    if (q < (n_edges - n_quads * 4))
        g_edge_src[g_offsets[dst[t]] + g_rank[t]] = src[t];
}

// ---------------- main gather-accumulate (R4 version) ----------------
// One warp per destination node; lane c owns float4 chunk c of the 128-wide row.
// After k_scan/k_scatter, [g_offsets[node], g_cursor[node]) is the edge range.

__global__ void __launch_bounds__(256)
k_gather(const float4* __restrict__ weight4,
         const float*  __restrict__ cj,
         const float*  __restrict__ ci,
         float4*       __restrict__ out4,
         int n_nodes)
{
    int gid  = blockIdx.x * blockDim.x + threadIdx.x;
    int node = gid >> 5;
    int c    = gid & 31;
    if (node >= n_nodes) return;

    int base = g_offsets[node];
    int end  = g_cursor[node];

    float4 acc = make_float4(0.f, 0.f, 0.f, 0.f);

    int j = base;
    for (; j + 3 < end; j += 4) {
        int s0 = g_edge_src[j];
        int s1 = g_edge_src[j + 1];
        int s2 = g_edge_src[j + 2];
        int s3 = g_edge_src[j + 3];
        float sc0 = __ldg(cj + s0);
        float sc1 = __ldg(cj + s1);
        float sc2 = __ldg(cj + s2);
        float sc3 = __ldg(cj + s3);
        float4 v0 = __ldg(weight4 + (int64_t)s0 * FEAT4 + c);
        float4 v1 = __ldg(weight4 + (int64_t)s1 * FEAT4 + c);
        float4 v2 = __ldg(weight4 + (int64_t)s2 * FEAT4 + c);
        float4 v3 = __ldg(weight4 + (int64_t)s3 * FEAT4 + c);
        acc.x += v0.x * sc0; acc.y += v0.y * sc0; acc.z += v0.z * sc0; acc.w += v0.w * sc0;
        acc.x += v1.x * sc1; acc.y += v1.y * sc1; acc.z += v1.z * sc1; acc.w += v1.w * sc1;
        acc.x += v2.x * sc2; acc.y += v2.y * sc2; acc.z += v2.z * sc2; acc.w += v2.w * sc2;
        acc.x += v3.x * sc3; acc.y += v3.y * sc3; acc.z += v3.z * sc3; acc.w += v3.w * sc3;
    }
    for (; j < end; j++) {
        int s0 = g_edge_src[j];
        float sc0 = __ldg(cj + s0);
        float4 v0 = __ldg(weight4 + (int64_t)s0 * FEAT4 + c);
        acc.x += v0.x * sc0; acc.y += v0.y * sc0; acc.z += v0.z * sc0; acc.w += v0.w * sc0;
    }

    float m = __ldg(ci + node);
    acc.x *= m; acc.y *= m; acc.z *= m; acc.w *= m;
    out4[(int64_t)node * FEAT4 + c] = acc;

    // restore zero-counts invariant for the next graph replay
    if (c == 0) g_counts[node] = 0;
}

// ---------------- launch ----------------

extern "C" void kernel_launch(void* const* d_in, const int* in_sizes, int n_in,
                              void* d_out, int out_size)
{
    const float4* weight4 = (const float4*)d_in[0];
    const float*  cj      = (const float*)d_in[1];
    const float*  ci      = (const float*)d_in[2];
    const int*    src     = (const int*)d_in[3];
    const int*    dst     = (const int*)d_in[4];
    float4*       out4    = (float4*)d_out;

    int n_nodes = in_sizes[1];   // cj is [N,1]
    int n_edges = in_sizes[3];
    int n_quads = n_edges / 4;

    const int B = 256;
    int quad_blocks = (n_quads + B - 1) / B;

    k_hist<<<quad_blocks, B>>>((const int4*)dst, n_quads, dst, n_edges);
    k_scan<<<1, 1024>>>(n_nodes);
    k_scatter<<<quad_blocks, B>>>((const int4*)src, (const int4*)dst, n_quads,
                                  src, dst, n_edges);

    int64_t total_threads = (int64_t)n_nodes * 32;
    int gather_blocks = (int)((total_threads + B - 1) / B);
    k_gather<<<gather_blocks, B>>>(weight4, cj, ci, out4, n_nodes);
}

// round 10
// speedup vs baseline: 2.6978x; 2.6978x over previous
#include <cuda_runtime.h>
#include <cuda_bf16.h>
#include <cstdint>

// Inputs (metadata order):
//   d_in[0] weight : float32 [N_NODES * 128]
//   d_in[1] cj     : float32 [N_NODES]
//   d_in[2] ci     : float32 [N_NODES]
//   d_in[3] src    : int32   [N_EDGES]
//   d_in[4] dst    : int32   [N_EDGES]
// Output: float32 [N_NODES * 128]
//
// h[d] = ci[d] * sum_{e: dst_e = d} weight[src_e] * cj[src_e]
//
// 4-kernel pipeline:
//   k_hist    : int4 histogram of dst; stores each edge's rank (the
//               atomicAdd return) coalesced into g_rank
//   k_scan    : exclusive scan, coalesced 1024-wide blocks; cross-block
//               prefix via publish/poll (proven replay-safe in R5's bench)
//   k_scatter : pos = offsets[dst] + rank (plain loads, no atomics)
//   k_gather  : one warp per dst node; per-edge broadcast id/cj loads,
//               4-deep unrolled float4 gathers, register accumulate, 1 store

static constexpr int MAX_NODES  = 100000;
static constexpr int MAX_EDGES  = 1600000;
static constexpr int FEAT4      = 32;           // 128 floats = 32 float4
static constexpr int SCAN_BLOCK = 1024;
static constexpr int MAX_SCAN_BLOCKS = (MAX_NODES + SCAN_BLOCK - 1) / SCAN_BLOCK; // 98

__device__ int g_counts[MAX_NODES];             // zero-init; re-zeroed by gather
__device__ int g_offsets[MAX_NODES];            // segment start
__device__ int g_cursor[MAX_NODES];             // segment end
__device__ unsigned int g_pub[MAX_SCAN_BLOCKS]; // zero-init; re-zeroed by scatter
__device__ int g_rank[MAX_EDGES];               // per-edge rank within its dst
__device__ int g_edge_src[MAX_EDGES];           // dst-sorted src ids

// ---------------- histogram with rank capture ----------------

__global__ void __launch_bounds__(256)
k_hist(const int4* __restrict__ dst4, int n_quads,
       const int* __restrict__ dst, int n_edges)
{
    int q = blockIdx.x * 256 + threadIdx.x;
    if (q < n_quads) {
        int4 d = __ldg(dst4 + q);
        int4 r;
        r.x = atomicAdd(&g_counts[d.x], 1);
        r.y = atomicAdd(&g_counts[d.y], 1);
        r.z = atomicAdd(&g_counts[d.z], 1);
        r.w = atomicAdd(&g_counts[d.w], 1);
        ((int4*)g_rank)[q] = r;                  // coalesced rank store
    }
    int t = n_quads * 4 + q;
    if (q < (n_edges - n_quads * 4))
        g_rank[t] = atomicAdd(&g_counts[dst[t]], 1);
}

// ---------------- exclusive scan (single launch, publish/poll) ----------------
// Exactly the structure that passed and replayed correctly in the R5 bench.
// 98 blocks of 1024 threads: co-resident on the SM pool, so the predecessor
// poll cannot deadlock. Block totals < 2^31; bit31 is the publish flag.

__global__ void __launch_bounds__(SCAN_BLOCK)
k_scan(int n) {
    __shared__ int warp_sums[32];
    __shared__ int s_prefix;
    int tid  = threadIdx.x;
    int i    = blockIdx.x * SCAN_BLOCK + tid;
    int lane = tid & 31, wid = tid >> 5;

    int v = (i < n) ? g_counts[i] : 0;

    int x = v;  // inclusive warp scan
    #pragma unroll
    for (int o = 1; o < 32; o <<= 1) {
        int y = __shfl_up_sync(0xFFFFFFFFu, x, o);
        if (lane >= o) x += y;
    }
    if (lane == 31) warp_sums[wid] = x;
    __syncthreads();

    if (wid == 0) {
        int w = warp_sums[lane];
        #pragma unroll
        for (int o = 1; o < 32; o <<= 1) {
            int y = __shfl_up_sync(0xFFFFFFFFu, w, o);
            if (lane >= o) w += y;
        }
        warp_sums[lane] = w;
        if (lane == 31)
            atomicExch(&g_pub[blockIdx.x], 0x80000000u | (unsigned)w);
    }
    __syncthreads();

    if (wid == 0) {
        int acc = 0;
        for (int b = lane; b < (int)blockIdx.x; b += 32) {
            unsigned int p;
            do { p = *(volatile unsigned int*)&g_pub[b]; }
            while (!(p & 0x80000000u));
            acc += (int)(p & 0x7FFFFFFFu);
        }
        #pragma unroll
        for (int o = 16; o > 0; o >>= 1)
            acc += __shfl_down_sync(0xFFFFFFFFu, acc, o);
        if (lane == 0) s_prefix = acc;
    }
    __syncthreads();

    int warp_off = (wid > 0) ? warp_sums[wid - 1] : 0;
    if (i < n) {
        int excl = s_prefix + warp_off + x - v;
        g_offsets[i] = excl;        // segment start
        g_cursor[i]  = excl + v;    // segment end
    }
}

// ---------------- scatter (atomic-free) ----------------

__global__ void __launch_bounds__(256)
k_scatter(const int4* __restrict__ src4,
          const int4* __restrict__ dst4, int n_quads,
          const int* __restrict__ src,
          const int* __restrict__ dst, int n_edges)
{
    int q = blockIdx.x * 256 + threadIdx.x;
    if (q < n_quads) {
        int4 s = __ldg(src4 + q);
        int4 d = __ldg(dst4 + q);
        int4 r = ((const int4*)g_rank)[q];
        g_edge_src[g_offsets[d.x] + r.x] = s.x;
        g_edge_src[g_offsets[d.y] + r.y] = s.y;
        g_edge_src[g_offsets[d.z] + r.z] = s.z;
        g_edge_src[g_offsets[d.w] + r.w] = s.w;
    }
    int t = n_quads * 4 + q;
    if (q < (n_edges - n_quads * 4))
        g_edge_src[g_offsets[dst[t]] + g_rank[t]] = src[t];

    // reset scan publish flags for the next graph replay
    if (blockIdx.x == 0 && threadIdx.x < MAX_SCAN_BLOCKS)
        g_pub[threadIdx.x] = 0u;
}

// ---------------- main gather-accumulate (proven 61us version) ----------------
// One warp per destination node; lane c owns float4 chunk c of the 128-wide row.
// After k_scan/k_scatter, [g_offsets[node], g_cursor[node]) is the edge range.

__global__ void __launch_bounds__(256)
k_gather(const float4* __restrict__ weight4,
         const float*  __restrict__ cj,
         const float*  __restrict__ ci,
         float4*       __restrict__ out4,
         int n_nodes)
{
    int gid  = blockIdx.x * blockDim.x + threadIdx.x;
    int node = gid >> 5;
    int c    = gid & 31;
    if (node >= n_nodes) return;

    int base = g_offsets[node];
    int end  = g_cursor[node];

    float4 acc = make_float4(0.f, 0.f, 0.f, 0.f);

    int j = base;
    for (; j + 3 < end; j += 4) {
        int s0 = g_edge_src[j];
        int s1 = g_edge_src[j + 1];
        int s2 = g_edge_src[j + 2];
        int s3 = g_edge_src[j + 3];
        float sc0 = __ldg(cj + s0);
        float sc1 = __ldg(cj + s1);
        float sc2 = __ldg(cj + s2);
        float sc3 = __ldg(cj + s3);
        float4 v0 = __ldg(weight4 + (int64_t)s0 * FEAT4 + c);
        float4 v1 = __ldg(weight4 + (int64_t)s1 * FEAT4 + c);
        float4 v2 = __ldg(weight4 + (int64_t)s2 * FEAT4 + c);
        float4 v3 = __ldg(weight4 + (int64_t)s3 * FEAT4 + c);
        acc.x += v0.x * sc0; acc.y += v0.y * sc0; acc.z += v0.z * sc0; acc.w += v0.w * sc0;
        acc.x += v1.x * sc1; acc.y += v1.y * sc1; acc.z += v1.z * sc1; acc.w += v1.w * sc1;
        acc.x += v2.x * sc2; acc.y += v2.y * sc2; acc.z += v2.z * sc2; acc.w += v2.w * sc2;
        acc.x += v3.x * sc3; acc.y += v3.y * sc3; acc.z += v3.z * sc3; acc.w += v3.w * sc3;
    }
    for (; j < end; j++) {
        int s0 = g_edge_src[j];
        float sc0 = __ldg(cj + s0);
        float4 v0 = __ldg(weight4 + (int64_t)s0 * FEAT4 + c);
        acc.x += v0.x * sc0; acc.y += v0.y * sc0; acc.z += v0.z * sc0; acc.w += v0.w * sc0;
    }

    float m = __ldg(ci + node);
    acc.x *= m; acc.y *= m; acc.z *= m; acc.w *= m;
    out4[(int64_t)node * FEAT4 + c] = acc;

    // restore zero-counts invariant for the next graph replay
    if (c == 0) g_counts[node] = 0;
}

// ---------------- launch ----------------

extern "C" void kernel_launch(void* const* d_in, const int* in_sizes, int n_in,
                              void* d_out, int out_size)
{
    const float4* weight4 = (const float4*)d_in[0];
    const float*  cj      = (const float*)d_in[1];
    const float*  ci      = (const float*)d_in[2];
    const int*    src     = (const int*)d_in[3];
    const int*    dst     = (const int*)d_in[4];
    float4*       out4    = (float4*)d_out;

    int n_nodes = in_sizes[1];   // cj is [N,1]
    int n_edges = in_sizes[3];
    int n_quads = n_edges / 4;

    const int B = 256;
    int quad_blocks = (n_quads + B - 1) / B;
    int scan_blocks = (n_nodes + SCAN_BLOCK - 1) / SCAN_BLOCK;

    k_hist<<<quad_blocks, B>>>((const int4*)dst, n_quads, dst, n_edges);
    k_scan<<<scan_blocks, SCAN_BLOCK>>>(n_nodes);
    k_scatter<<<quad_blocks, B>>>((const int4*)src, (const int4*)dst, n_quads,
                                  src, dst, n_edges);

    int64_t total_threads = (int64_t)n_nodes * 32;
    int gather_blocks = (int)((total_threads + B - 1) / B);
    k_gather<<<gather_blocks, B>>>(weight4, cj, ci, out4, n_nodes);
}